// round 15
// baseline (speedup 1.0000x reference)
#include <cuda_runtime.h>

// Problem constants (from reference)
#define Nn   1024
#define Mm   1024
#define Ff   1024
#define Ee   64
#define Gg   16
#define EPSv 1e-6f
#define BMAX 2

// Scratch (device globals: allocation-free contract)
// g_QKV layout: row r = b*Nn+n, 3072 cols: [0,1024)=Q, [1024,2048)=K, [2048,3072)=V
__device__ float g_QKV[BMAX * Nn * 3072];
// g_S layout: [(b*G+g)][n][m]
__device__ float g_S[BMAX * Gg * Nn * Mm];
__device__ float g_inv[BMAX * Gg * Nn];

// ---------------------------------------------------------------------------
// Kernel 1: C[r, coff+c] = sum_f A[r,f] * W[c,f] + bias[c]   (A, W both K-major)
// 128x128 tile, BK=8, 256 threads, 8x8 per thread. Writes into g_QKV (ldc=3072).
// ---------------------------------------------------------------------------
__global__ __launch_bounds__(256) void qkv_gemm(const float* __restrict__ A,
                                                const float* __restrict__ W,
                                                const float* __restrict__ bias,
                                                int coff)
{
    __shared__ float As[8][128];
    __shared__ float Ws[8][128];
    const int tid  = threadIdx.x;
    const int row0 = blockIdx.y * 128;
    const int col0 = blockIdx.x * 128;
    const int lrow = tid >> 1;
    const int lc4  = (tid & 1) * 4;
    const float* Ap = A + (size_t)(row0 + lrow) * Ff + lc4;
    const float* Wp = W + (size_t)(col0 + lrow) * Ff + lc4;
    const int tx = tid & 15, ty = tid >> 4;

    float acc[8][8];
#pragma unroll
    for (int i = 0; i < 8; i++)
#pragma unroll
        for (int j = 0; j < 8; j++) acc[i][j] = 0.f;

    for (int k0 = 0; k0 < Ff; k0 += 8) {
        float4 av = *(const float4*)(Ap + k0);
        float4 wv = *(const float4*)(Wp + k0);
        As[lc4 + 0][lrow] = av.x; As[lc4 + 1][lrow] = av.y;
        As[lc4 + 2][lrow] = av.z; As[lc4 + 3][lrow] = av.w;
        Ws[lc4 + 0][lrow] = wv.x; Ws[lc4 + 1][lrow] = wv.y;
        Ws[lc4 + 2][lrow] = wv.z; Ws[lc4 + 3][lrow] = wv.w;
        __syncthreads();
#pragma unroll
        for (int kk = 0; kk < 8; kk++) {
            float a[8], w[8];
            *(float4*)(a)     = *(const float4*)(&As[kk][ty * 8]);
            *(float4*)(a + 4) = *(const float4*)(&As[kk][ty * 8 + 4]);
            *(float4*)(w)     = *(const float4*)(&Ws[kk][tx * 8]);
            *(float4*)(w + 4) = *(const float4*)(&Ws[kk][tx * 8 + 4]);
#pragma unroll
            for (int i = 0; i < 8; i++)
#pragma unroll
                for (int j = 0; j < 8; j++)
                    acc[i][j] += a[i] * w[j];
        }
        __syncthreads();
    }

    float bv[8];
#pragma unroll
    for (int j = 0; j < 8; j++) bv[j] = bias ? bias[col0 + tx * 8 + j] : 0.f;

#pragma unroll
    for (int i = 0; i < 8; i++) {
        float* Crow = g_QKV + (size_t)(row0 + ty * 8 + i) * 3072 + coff + col0 + tx * 8;
        float4 v0, v1;
        v0.x = acc[i][0] + bv[0]; v0.y = acc[i][1] + bv[1];
        v0.z = acc[i][2] + bv[2]; v0.w = acc[i][3] + bv[3];
        v1.x = acc[i][4] + bv[4]; v1.y = acc[i][5] + bv[5];
        v1.z = acc[i][6] + bv[6]; v1.w = acc[i][7] + bv[7];
        *(float4*)(Crow)     = v0;
        *(float4*)(Crow + 4) = v1;
    }
}

// ---------------------------------------------------------------------------
// Kernel 2: S[z=b*G+g][n][m] = 0.125 * sum_d Q[b,n,g*64+d] * K[b,m,g*64+d]
// block = 64x64 (n,m) tile, full K=64 in shared, 4x4 per thread.
// ---------------------------------------------------------------------------
__global__ __launch_bounds__(256) void aff_kernel()
{
    __shared__ float Qs[64][65];
    __shared__ float Ks[64][65];
    const int tid = threadIdx.x;
    const int z   = blockIdx.z;
    const int b   = z >> 4, g = z & 15;
    const int n0  = blockIdx.y * 64;
    const int m0  = blockIdx.x * 64;
    const float* Qb = g_QKV + (size_t)b * Nn * 3072 + g * 64;
    const float* Kb = Qb + 1024;

#pragma unroll
    for (int r = 0; r < 4; r++) {
        int i4 = tid + 256 * r;
        int rr = i4 >> 4;
        int c4 = (i4 & 15) * 4;
        float4 q = *(const float4*)(Qb + (size_t)(n0 + rr) * 3072 + c4);
        Qs[rr][c4 + 0] = q.x; Qs[rr][c4 + 1] = q.y;
        Qs[rr][c4 + 2] = q.z; Qs[rr][c4 + 3] = q.w;
        float4 k = *(const float4*)(Kb + (size_t)(m0 + rr) * 3072 + c4);
        Ks[rr][c4 + 0] = k.x; Ks[rr][c4 + 1] = k.y;
        Ks[rr][c4 + 2] = k.z; Ks[rr][c4 + 3] = k.w;
    }
    __syncthreads();

    const int tx = tid & 15, ty = tid >> 4;
    float acc[4][4] = {};
#pragma unroll 16
    for (int d = 0; d < 64; d++) {
        float qv[4], kv[4];
#pragma unroll
        for (int i = 0; i < 4; i++) qv[i] = Qs[ty * 4 + i][d];
#pragma unroll
        for (int j = 0; j < 4; j++) kv[j] = Ks[tx * 4 + j][d];
#pragma unroll
        for (int i = 0; i < 4; i++)
#pragma unroll
            for (int j = 0; j < 4; j++) acc[i][j] += qv[i] * kv[j];
    }

    float* Sp = g_S + ((size_t)z * Nn + n0 + ty * 4) * Mm + m0 + tx * 4;
#pragma unroll
    for (int i = 0; i < 4; i++) {
        float4 v;
        v.x = 0.125f * acc[i][0]; v.y = 0.125f * acc[i][1];
        v.z = 0.125f * acc[i][2]; v.w = 0.125f * acc[i][3];
        *(float4*)(Sp + (size_t)i * Mm) = v;
    }
}

// ---------------------------------------------------------------------------
// Kernel 3: S[z][n][m] <- max(pe[b,n,m,:] . pos_w[g] + pos_b[g], eps) * exp(S[z][n][m])
// (softmax(log(max(w,eps)) + aff) == w~ * exp(aff) / sum;  max(relu(x),eps)==max(x,eps))
// block = (b, n, 64 m's); all 16 g handled per block so pe is read exactly once.
// ---------------------------------------------------------------------------
__global__ __launch_bounds__(256) void posexp_kernel(const float* __restrict__ pe,
                                                     const float* __restrict__ pw,
                                                     const float* __restrict__ pb)
{
    __shared__ float pe_s[64][65];
    __shared__ float pw_s[Gg * Ee];
    __shared__ float pb_s[Gg];
    const int tid = threadIdx.x;
    const int m0  = blockIdx.x * 64;
    const int n   = blockIdx.y;
    const int b   = blockIdx.z;

    for (int i = tid; i < Gg * Ee; i += 256) pw_s[i] = pw[i];
    if (tid < Gg) pb_s[tid] = pb[tid];

    const float4* src = (const float4*)(pe + (((size_t)(b * Nn + n)) * Mm + m0) * Ee);
#pragma unroll
    for (int r = 0; r < 4; r++) {
        int i4 = tid + 256 * r;
        float4 v = src[i4];
        int mm = i4 >> 4;
        int e4 = (i4 & 15) * 4;
        pe_s[mm][e4 + 0] = v.x; pe_s[mm][e4 + 1] = v.y;
        pe_s[mm][e4 + 2] = v.z; pe_s[mm][e4 + 3] = v.w;
    }
    __syncthreads();

    const int m  = tid & 63;
    const int gb = (tid >> 6) * 4;
    float acc0 = 0.f, acc1 = 0.f, acc2 = 0.f, acc3 = 0.f;
#pragma unroll 16
    for (int e = 0; e < 64; e++) {
        float pv = pe_s[m][e];
        acc0 += pv * pw_s[(gb + 0) * Ee + e];
        acc1 += pv * pw_s[(gb + 1) * Ee + e];
        acc2 += pv * pw_s[(gb + 2) * Ee + e];
        acc3 += pv * pw_s[(gb + 3) * Ee + e];
    }
    float accs[4] = {acc0, acc1, acc2, acc3};
    size_t base = ((size_t)(b * Gg + gb) * Nn + n) * Mm + m0 + m;
#pragma unroll
    for (int p = 0; p < 4; p++) {
        float w = fmaxf(accs[p] + pb_s[gb + p], EPSv);
        size_t idx = base + (size_t)p * Nn * Mm;
        g_S[idx] = w * __expf(g_S[idx]);
    }
}

// ---------------------------------------------------------------------------
// Kernel 4: g_inv[row] = 1 / sum_m g_S[row][m]     (row = (b*G+g)*N + n)
// ---------------------------------------------------------------------------
__global__ __launch_bounds__(256) void rowsum_kernel()
{
    const int row  = blockIdx.x;
    const float* p = g_S + (size_t)row * Mm;
    float s = 0.f;
    for (int j = threadIdx.x; j < Mm; j += 256) s += p[j];
#pragma unroll
    for (int o = 16; o > 0; o >>= 1) s += __shfl_xor_sync(0xffffffffu, s, o);
    __shared__ float red[8];
    if ((threadIdx.x & 31) == 0) red[threadIdx.x >> 5] = s;
    __syncthreads();
    if (threadIdx.x == 0) {
        float t = 0.f;
#pragma unroll
        for (int i = 0; i < 8; i++) t += red[i];
        g_inv[row] = 1.f / t;
    }
}

// ---------------------------------------------------------------------------
// Kernel 5: out[b,n,g*64+o] = inv[z,n] * sum_m S[z][n][m] * V[b,m,g*64+o] + conv_b[g*64+o]
// block = (32 n's) x (64 o's) for one (b,g); loops m in chunks of 64.
// ---------------------------------------------------------------------------
__global__ __launch_bounds__(256) void pv_kernel(const float* __restrict__ cb,
                                                 float* __restrict__ out)
{
    __shared__ float Ps[32][64];
    __shared__ float Vs[64][64];
    const int tid = threadIdx.x;
    const int z   = blockIdx.y;
    const int b   = z >> 4, g = z & 15;
    const int n0  = blockIdx.x * 32;
    const int o   = (tid & 31) * 2;
    const int nz  = tid >> 5;  // 0..7, each handles 4 n's
    const float* Vb = g_QKV + (size_t)b * Nn * 3072 + 2048 + g * 64;
    const float* Pb = g_S + ((size_t)z * Nn + n0) * Mm;

    float acc[4][2] = {};
    for (int m0 = 0; m0 < Mm; m0 += 64) {
#pragma unroll
        for (int r = 0; r < 2; r++) {
            int i4 = tid + 256 * r;
            int nn = i4 >> 4, mm4 = (i4 & 15) * 4;
            *(float4*)(&Ps[nn][mm4]) = *(const float4*)(Pb + (size_t)nn * Mm + m0 + mm4);
        }
#pragma unroll
        for (int r = 0; r < 4; r++) {
            int i4 = tid + 256 * r;
            int mm = i4 >> 4, o4 = (i4 & 15) * 4;
            *(float4*)(&Vs[mm][o4]) = *(const float4*)(Vb + (size_t)(m0 + mm) * 3072 + o4);
        }
        __syncthreads();
#pragma unroll 16
        for (int mm = 0; mm < 64; mm++) {
            float2 vv = *(const float2*)(&Vs[mm][o]);
#pragma unroll
            for (int i = 0; i < 4; i++) {
                float pp = Ps[nz * 4 + i][mm];
                acc[i][0] += pp * vv.x;
                acc[i][1] += pp * vv.y;
            }
        }
        __syncthreads();
    }

#pragma unroll
    for (int i = 0; i < 4; i++) {
        int n = n0 + nz * 4 + i;
        float iv = g_inv[(size_t)z * Nn + n];
        float2 res;
        res.x = acc[i][0] * iv + cb[g * 64 + o];
        res.y = acc[i][1] * iv + cb[g * 64 + o + 1];
        *(float2*)(&out[(size_t)(b * Nn + n) * 1024 + g * 64 + o]) = res;
    }
}

// ---------------------------------------------------------------------------
extern "C" void kernel_launch(void* const* d_in, const int* in_sizes, int n_in,
                              void* d_out, int out_size)
{
    const float* roi = (const float*)d_in[0];
    const float* pe  = (const float*)d_in[1];
    const float* pw  = (const float*)d_in[2];
    const float* pb  = (const float*)d_in[3];
    const float* qw  = (const float*)d_in[4];
    const float* qb  = (const float*)d_in[5];
    const float* kw  = (const float*)d_in[6];
    const float* kb  = (const float*)d_in[7];
    const float* cw  = (const float*)d_in[8];
    const float* cb  = (const float*)d_in[9];
    float* out = (float*)d_out;

    const int Bb = in_sizes[0] / (Nn * Ff);  // batch (2)

    // 1) Q, K, V projections into g_QKV (V without bias; conv_b added in epilogue)
    dim3 gq(1024 / 128, (Bb * Nn) / 128);
    qkv_gemm<<<gq, 256>>>(roi, qw, qb, 0);
    qkv_gemm<<<gq, 256>>>(roi, kw, kb, 1024);
    qkv_gemm<<<gq, 256>>>(roi, cw, (const float*)nullptr, 2048);

    // 2) grouped q.k logits (scaled)
    aff_kernel<<<dim3(Mm / 64, Nn / 64, Bb * Gg), 256>>>();

    // 3) fused position-embedding dot + relu/eps clamp + exp (unnormalized softmax)
    posexp_kernel<<<dim3(Mm / 64, Nn, Bb), 256>>>(pe, pw, pb);

    // 4) row sums -> reciprocals
    rowsum_kernel<<<Bb * Gg * Nn, 256>>>();

    // 5) grouped P @ V with normalization + conv bias
    pv_kernel<<<dim3(Nn / 32, Bb * Gg), 256>>>(cb, out);
}

// round 16
// speedup vs baseline: 1.3669x; 1.3669x over previous
#include <cuda_runtime.h>

#define Nn   1024
#define Mm   1024
#define Ff   1024
#define Ee   64
#define Gg   16
#define EPSv 1e-6f
#define BMAX 2

// Scratch (device globals: allocation-free contract)
// g_QKV: row r = b*Nn+n, 3072 cols: [0,1024)=Q, [1024,2048)=K, [2048,3072)=V
__device__ float g_QKV[BMAX * Nn * 3072];
// g_S: [(b*G+g)][n][m].  Written by posw (= clamped pos weights), then
// overwritten in-place by aff_fused (= w * exp(qk/8)).
__device__ float g_S[BMAX * Gg * Nn * Mm];
__device__ float g_sum[BMAX * Gg * Nn];

// ---------------------------------------------------------------------------
// Kernel 0: zero the row-sum accumulators
// ---------------------------------------------------------------------------
__global__ void init_sums(int total)
{
    int i = blockIdx.x * blockDim.x + threadIdx.x;
    if (i < total) g_sum[i] = 0.f;
}

// ---------------------------------------------------------------------------
// Kernel 1 (fused Q/K/V): C[r, which*1024+c] = sum_f A[r,f]*W[c,f] (+bias)
// 128x128 tile, BK=16, 256 threads, 8x8 per thread. which = blockIdx.x>>3.
// ---------------------------------------------------------------------------
__global__ __launch_bounds__(256) void qkv_gemm_all(const float* __restrict__ A,
                                                    const float* __restrict__ qw,
                                                    const float* __restrict__ kw,
                                                    const float* __restrict__ cw,
                                                    const float* __restrict__ qb,
                                                    const float* __restrict__ kb)
{
    __shared__ float As[16][132];
    __shared__ float Ws[16][132];
    const int tid   = threadIdx.x;
    const int which = blockIdx.x >> 3;            // 0=Q 1=K 2=V
    const int col0  = (blockIdx.x & 7) * 128;
    const int row0  = blockIdx.y * 128;
    const float* W    = (which == 0) ? qw : (which == 1) ? kw : cw;
    const float* bias = (which == 0) ? qb : (which == 1) ? kb : (const float*)0;

    const int tx = tid & 15, ty = tid >> 4;

    float acc[8][8];
#pragma unroll
    for (int i = 0; i < 8; i++)
#pragma unroll
        for (int j = 0; j < 8; j++) acc[i][j] = 0.f;

    for (int k0 = 0; k0 < Ff; k0 += 16) {
#pragma unroll
        for (int r = 0; r < 2; r++) {
            int i4 = tid + 256 * r;
            int rr = i4 >> 2;
            int c4 = (i4 & 3) * 4;
            float4 av = *(const float4*)(A + (size_t)(row0 + rr) * Ff + k0 + c4);
            float4 wv = *(const float4*)(W + (size_t)(col0 + rr) * Ff + k0 + c4);
            As[c4 + 0][rr] = av.x; As[c4 + 1][rr] = av.y;
            As[c4 + 2][rr] = av.z; As[c4 + 3][rr] = av.w;
            Ws[c4 + 0][rr] = wv.x; Ws[c4 + 1][rr] = wv.y;
            Ws[c4 + 2][rr] = wv.z; Ws[c4 + 3][rr] = wv.w;
        }
        __syncthreads();
#pragma unroll
        for (int kk = 0; kk < 16; kk++) {
            float a[8], w[8];
            *(float4*)(a)     = *(const float4*)(&As[kk][ty * 8]);
            *(float4*)(a + 4) = *(const float4*)(&As[kk][ty * 8 + 4]);
            *(float4*)(w)     = *(const float4*)(&Ws[kk][tx * 8]);
            *(float4*)(w + 4) = *(const float4*)(&Ws[kk][tx * 8 + 4]);
#pragma unroll
            for (int i = 0; i < 8; i++)
#pragma unroll
                for (int j = 0; j < 8; j++)
                    acc[i][j] += a[i] * w[j];
        }
        __syncthreads();
    }

    float bv[8];
#pragma unroll
    for (int j = 0; j < 8; j++) bv[j] = bias ? bias[col0 + tx * 8 + j] : 0.f;

    const int coff = which * 1024 + col0;
#pragma unroll
    for (int i = 0; i < 8; i++) {
        float* Crow = g_QKV + (size_t)(row0 + ty * 8 + i) * 3072 + coff + tx * 8;
        float4 v0, v1;
        v0.x = acc[i][0] + bv[0]; v0.y = acc[i][1] + bv[1];
        v0.z = acc[i][2] + bv[2]; v0.w = acc[i][3] + bv[3];
        v1.x = acc[i][4] + bv[4]; v1.y = acc[i][5] + bv[5];
        v1.z = acc[i][6] + bv[6]; v1.w = acc[i][7] + bv[7];
        *(float4*)(Crow)     = v0;
        *(float4*)(Crow + 4) = v1;
    }
}

// ---------------------------------------------------------------------------
// Kernel 2: g_S[z][n][m] = max(pe[b,n,m,:].pos_w[g] + pos_b[g], eps)
// block = (b, n, 64 m's); all 16 g per block so pe is read exactly once.
// Vectorized inner loop: float4 smem reads.
// ---------------------------------------------------------------------------
__global__ __launch_bounds__(256) void posw_kernel(const float* __restrict__ pe,
                                                   const float* __restrict__ pw,
                                                   const float* __restrict__ pb)
{
    __shared__ float pe_s[64][68];
    __shared__ float pw_s[Gg * Ee];
    __shared__ float pb_s[Gg];
    const int tid = threadIdx.x;
    const int m0  = blockIdx.x * 64;
    const int n   = blockIdx.y;
    const int b   = blockIdx.z;

    for (int i = tid; i < Gg * Ee; i += 256) pw_s[i] = pw[i];
    if (tid < Gg) pb_s[tid] = pb[tid];

    const float4* src = (const float4*)(pe + (((size_t)(b * Nn + n)) * Mm + m0) * Ee);
#pragma unroll
    for (int r = 0; r < 4; r++) {
        int i4 = tid + 256 * r;
        float4 v = src[i4];
        int mm = i4 >> 4;
        int e4 = (i4 & 15) * 4;
        pe_s[mm][e4 + 0] = v.x; pe_s[mm][e4 + 1] = v.y;
        pe_s[mm][e4 + 2] = v.z; pe_s[mm][e4 + 3] = v.w;
    }
    __syncthreads();

    const int m  = tid & 63;
    const int gb = (tid >> 6) * 4;
    float acc[4] = {0.f, 0.f, 0.f, 0.f};
#pragma unroll
    for (int e0 = 0; e0 < 64; e0 += 4) {
        float4 pv = *(const float4*)(&pe_s[m][e0]);
#pragma unroll
        for (int p = 0; p < 4; p++) {
            float4 w4 = *(const float4*)(&pw_s[(gb + p) * Ee + e0]);
            acc[p] += pv.x * w4.x + pv.y * w4.y + pv.z * w4.z + pv.w * w4.w;
        }
    }
    size_t base = ((size_t)(b * Gg + gb) * Nn + n) * Mm + m0 + m;
#pragma unroll
    for (int p = 0; p < 4; p++) {
        g_S[base + (size_t)p * Nn * Mm] = fmaxf(acc[p] + pb_s[gb + p], EPSv);
    }
}

// ---------------------------------------------------------------------------
// Kernel 3: aff + exp + weight + rowsum, fused.
// S[z][n][m] <- S[z][n][m] * exp(0.125 * q.k);  g_sum[z][n] += row sum.
// 128x128 tile per block, 8x8 per thread, K=64 in two 32-chunks.
// ---------------------------------------------------------------------------
__global__ __launch_bounds__(256) void aff_fused()
{
    __shared__ float Qs[32][132];
    __shared__ float Ks[32][132];
    const int tid = threadIdx.x;
    const int z   = blockIdx.z;
    const int b   = z >> 4, g = z & 15;
    const int n0  = blockIdx.y * 128;
    const int m0  = blockIdx.x * 128;
    const float* Qb = g_QKV + (size_t)b * Nn * 3072 + g * 64;
    const float* Kb = Qb + 1024;
    const int tx = tid & 15, ty = tid >> 4;

    float acc[8][8];
#pragma unroll
    for (int i = 0; i < 8; i++)
#pragma unroll
        for (int j = 0; j < 8; j++) acc[i][j] = 0.f;

    for (int d0 = 0; d0 < 64; d0 += 32) {
#pragma unroll
        for (int r = 0; r < 4; r++) {
            int i4 = tid + 256 * r;
            int rr = i4 >> 3;
            int c4 = (i4 & 7) * 4;
            float4 q = *(const float4*)(Qb + (size_t)(n0 + rr) * 3072 + d0 + c4);
            float4 k = *(const float4*)(Kb + (size_t)(m0 + rr) * 3072 + d0 + c4);
            Qs[c4 + 0][rr] = q.x; Qs[c4 + 1][rr] = q.y;
            Qs[c4 + 2][rr] = q.z; Qs[c4 + 3][rr] = q.w;
            Ks[c4 + 0][rr] = k.x; Ks[c4 + 1][rr] = k.y;
            Ks[c4 + 2][rr] = k.z; Ks[c4 + 3][rr] = k.w;
        }
        __syncthreads();
#pragma unroll
        for (int kk = 0; kk < 32; kk++) {
            float a[8], w[8];
            *(float4*)(a)     = *(const float4*)(&Qs[kk][ty * 8]);
            *(float4*)(a + 4) = *(const float4*)(&Qs[kk][ty * 8 + 4]);
            *(float4*)(w)     = *(const float4*)(&Ks[kk][tx * 8]);
            *(float4*)(w + 4) = *(const float4*)(&Ks[kk][tx * 8 + 4]);
#pragma unroll
            for (int i = 0; i < 8; i++)
#pragma unroll
                for (int j = 0; j < 8; j++)
                    acc[i][j] += a[i] * w[j];
        }
        __syncthreads();
    }

    // Epilogue: read weights, apply exp, write back, accumulate row sums.
#pragma unroll
    for (int i = 0; i < 8; i++) {
        int row = n0 + ty * 8 + i;
        float* Sp = g_S + ((size_t)z * Nn + row) * Mm + m0 + tx * 8;
        float4 w0 = *(const float4*)(Sp);
        float4 w1 = *(const float4*)(Sp + 4);
        float4 o0, o1;
        o0.x = w0.x * __expf(0.125f * acc[i][0]);
        o0.y = w0.y * __expf(0.125f * acc[i][1]);
        o0.z = w0.z * __expf(0.125f * acc[i][2]);
        o0.w = w0.w * __expf(0.125f * acc[i][3]);
        o1.x = w1.x * __expf(0.125f * acc[i][4]);
        o1.y = w1.y * __expf(0.125f * acc[i][5]);
        o1.z = w1.z * __expf(0.125f * acc[i][6]);
        o1.w = w1.w * __expf(0.125f * acc[i][7]);
        *(float4*)(Sp)     = o0;
        *(float4*)(Sp + 4) = o1;

        float rs = o0.x + o0.y + o0.z + o0.w + o1.x + o1.y + o1.z + o1.w;
        // reduce across the 16 tx lanes (lane = (ty&1)*16 + tx)
        rs += __shfl_xor_sync(0xffffffffu, rs, 1);
        rs += __shfl_xor_sync(0xffffffffu, rs, 2);
        rs += __shfl_xor_sync(0xffffffffu, rs, 4);
        rs += __shfl_xor_sync(0xffffffffu, rs, 8);
        if (tx == 0)
            atomicAdd(&g_sum[(size_t)z * Nn + row], rs);
    }
}

// ---------------------------------------------------------------------------
// Kernel 4: out[b,n,g*64+o] = (1/sum[z,n]) * sum_m S[z][n][m] * V[b,m,g*64+o]
//                             + conv_b[g*64+o]
// 128n x 64o tile per (b,g); 8x4 per thread; m in chunks of 32 (P transposed).
// ---------------------------------------------------------------------------
__global__ __launch_bounds__(256) void pv_kernel(const float* __restrict__ cb,
                                                 float* __restrict__ out)
{
    __shared__ float Ps[32][132];
    __shared__ float Vs[32][68];
    const int tid = threadIdx.x;
    const int z   = blockIdx.y;
    const int b   = z >> 4, g = z & 15;
    const int n0  = blockIdx.x * 128;
    const int tx  = tid & 15, ty = tid >> 4;
    const float* Vb = g_QKV + (size_t)b * Nn * 3072 + 2048 + g * 64;
    const float* Pb = g_S + ((size_t)z * Nn + n0) * Mm;

    float acc[8][4];
#pragma unroll
    for (int i = 0; i < 8; i++)
#pragma unroll
        for (int j = 0; j < 4; j++) acc[i][j] = 0.f;

    for (int m0 = 0; m0 < Mm; m0 += 32) {
#pragma unroll
        for (int r = 0; r < 4; r++) {
            int i4 = tid + 256 * r;
            int rr = i4 >> 3;           // n index 0..127
            int c4 = (i4 & 7) * 4;      // m offset 0..28
            float4 p = *(const float4*)(Pb + (size_t)rr * Mm + m0 + c4);
            Ps[c4 + 0][rr] = p.x; Ps[c4 + 1][rr] = p.y;
            Ps[c4 + 2][rr] = p.z; Ps[c4 + 3][rr] = p.w;
        }
#pragma unroll
        for (int r = 0; r < 2; r++) {
            int i4 = tid + 256 * r;
            int mm = i4 >> 4;           // m offset 0..31
            int o4 = (i4 & 15) * 4;     // o 0..60
            *(float4*)(&Vs[mm][o4]) =
                *(const float4*)(Vb + (size_t)(m0 + mm) * 3072 + o4);
        }
        __syncthreads();
#pragma unroll
        for (int kk = 0; kk < 32; kk++) {
            float a[8];
            *(float4*)(a)     = *(const float4*)(&Ps[kk][ty * 8]);
            *(float4*)(a + 4) = *(const float4*)(&Ps[kk][ty * 8 + 4]);
            float4 v = *(const float4*)(&Vs[kk][tx * 4]);
#pragma unroll
            for (int i = 0; i < 8; i++) {
                acc[i][0] += a[i] * v.x;
                acc[i][1] += a[i] * v.y;
                acc[i][2] += a[i] * v.z;
                acc[i][3] += a[i] * v.w;
            }
        }
        __syncthreads();
    }

    float b0 = cb[g * 64 + tx * 4 + 0];
    float b1 = cb[g * 64 + tx * 4 + 1];
    float b2 = cb[g * 64 + tx * 4 + 2];
    float b3 = cb[g * 64 + tx * 4 + 3];
#pragma unroll
    for (int i = 0; i < 8; i++) {
        int row = n0 + ty * 8 + i;
        float iv = 1.0f / g_sum[(size_t)z * Nn + row];
        float4 res;
        res.x = acc[i][0] * iv + b0;
        res.y = acc[i][1] * iv + b1;
        res.z = acc[i][2] * iv + b2;
        res.w = acc[i][3] * iv + b3;
        *(float4*)(&out[(size_t)(b * Nn + row) * 1024 + g * 64 + tx * 4]) = res;
    }
}

// ---------------------------------------------------------------------------
extern "C" void kernel_launch(void* const* d_in, const int* in_sizes, int n_in,
                              void* d_out, int out_size)
{
    const float* roi = (const float*)d_in[0];
    const float* pe  = (const float*)d_in[1];
    const float* pw  = (const float*)d_in[2];
    const float* pb  = (const float*)d_in[3];
    const float* qw  = (const float*)d_in[4];
    const float* qb  = (const float*)d_in[5];
    const float* kw  = (const float*)d_in[6];
    const float* kb  = (const float*)d_in[7];
    const float* cw  = (const float*)d_in[8];
    const float* cb  = (const float*)d_in[9];
    float* out = (float*)d_out;

    const int Bb = in_sizes[0] / (Nn * Ff);  // batch (2)

    // 0) zero row-sum accumulators
    init_sums<<<(Bb * Gg * Nn + 255) / 256, 256>>>(Bb * Gg * Nn);

    // 1) Q, K, V projections (one launch; V bias = conv_b handled in pv epilogue)
    qkv_gemm_all<<<dim3(24, (Bb * Nn) / 128), 256>>>(roi, qw, kw, cw, qb, kb);

    // 2) clamped position weights -> g_S   (reads pe exactly once)
    posw_kernel<<<dim3(Mm / 64, Nn, Bb), 256>>>(pe, pw, pb);

    // 3) q.k logits + exp + weight + row sums, fused, in-place on g_S
    aff_fused<<<dim3(Mm / 128, Nn / 128, Bb * Gg), 256>>>();

    // 4) grouped P @ V with normalization + conv bias
    pv_kernel<<<dim3(Nn / 128, Bb * Gg), 256>>>(cb, out);
}

// round 17
// speedup vs baseline: 1.3680x; 1.0008x over previous
#include <cuda_runtime.h>

#define Nn   1024
#define Mm   1024
#define Ff   1024
#define Ee   64
#define Gg   16
#define EPSv 1e-6f
#define BMAX 2

// Scratch (device globals: allocation-free contract)
// g_QKV: row r = b*Nn+n, 3072 cols: [0,1024)=Q, [1024,2048)=K, [2048,3072)=V
__device__ float g_QKV[BMAX * Nn * 3072];
// g_S: [(b*G+g)][n][m].  Written by posw (= clamped pos weights), then
// overwritten in-place by aff_fused (= w * exp(qk/8)).
__device__ float g_S[BMAX * Gg * Nn * Mm];
__device__ float g_sum[BMAX * Gg * Nn];

// ---------------------------------------------------------------------------
// Kernel 0: zero the row-sum accumulators
// ---------------------------------------------------------------------------
__global__ void init_sums(int total)
{
    int i = blockIdx.x * blockDim.x + threadIdx.x;
    if (i < total) g_sum[i] = 0.f;
}

// ---------------------------------------------------------------------------
// Kernel 1 (fused Q/K/V): C[r, which*1024+c] = sum_f A[r,f]*W[c,f] (+bias)
// 128x128 tile, BK=16, 256 threads, 8x8 per thread. which = blockIdx.x>>3.
// ---------------------------------------------------------------------------
__global__ __launch_bounds__(256) void qkv_gemm_all(const float* __restrict__ A,
                                                    const float* __restrict__ qw,
                                                    const float* __restrict__ kw,
                                                    const float* __restrict__ cw,
                                                    const float* __restrict__ qb,
                                                    const float* __restrict__ kb)
{
    __shared__ float As[16][132];
    __shared__ float Ws[16][132];
    const int tid   = threadIdx.x;
    const int which = blockIdx.x >> 3;            // 0=Q 1=K 2=V
    const int col0  = (blockIdx.x & 7) * 128;
    const int row0  = blockIdx.y * 128;
    const float* W    = (which == 0) ? qw : (which == 1) ? kw : cw;
    const float* bias = (which == 0) ? qb : (which == 1) ? kb : (const float*)0;

    const int tx = tid & 15, ty = tid >> 4;

    float acc[8][8];
#pragma unroll
    for (int i = 0; i < 8; i++)
#pragma unroll
        for (int j = 0; j < 8; j++) acc[i][j] = 0.f;

    for (int k0 = 0; k0 < Ff; k0 += 16) {
#pragma unroll
        for (int r = 0; r < 2; r++) {
            int i4 = tid + 256 * r;
            int rr = i4 >> 2;
            int c4 = (i4 & 3) * 4;
            float4 av = *(const float4*)(A + (size_t)(row0 + rr) * Ff + k0 + c4);
            float4 wv = *(const float4*)(W + (size_t)(col0 + rr) * Ff + k0 + c4);
            As[c4 + 0][rr] = av.x; As[c4 + 1][rr] = av.y;
            As[c4 + 2][rr] = av.z; As[c4 + 3][rr] = av.w;
            Ws[c4 + 0][rr] = wv.x; Ws[c4 + 1][rr] = wv.y;
            Ws[c4 + 2][rr] = wv.z; Ws[c4 + 3][rr] = wv.w;
        }
        __syncthreads();
#pragma unroll
        for (int kk = 0; kk < 16; kk++) {
            float a[8], w[8];
            *(float4*)(a)     = *(const float4*)(&As[kk][ty * 8]);
            *(float4*)(a + 4) = *(const float4*)(&As[kk][ty * 8 + 4]);
            *(float4*)(w)     = *(const float4*)(&Ws[kk][tx * 8]);
            *(float4*)(w + 4) = *(const float4*)(&Ws[kk][tx * 8 + 4]);
#pragma unroll
            for (int i = 0; i < 8; i++)
#pragma unroll
                for (int j = 0; j < 8; j++)
                    acc[i][j] += a[i] * w[j];
        }
        __syncthreads();
    }

    float bv[8];
#pragma unroll
    for (int j = 0; j < 8; j++) bv[j] = bias ? bias[col0 + tx * 8 + j] : 0.f;

    const int coff = which * 1024 + col0;
#pragma unroll
    for (int i = 0; i < 8; i++) {
        float* Crow = g_QKV + (size_t)(row0 + ty * 8 + i) * 3072 + coff + tx * 8;
        float4 v0, v1;
        v0.x = acc[i][0] + bv[0]; v0.y = acc[i][1] + bv[1];
        v0.z = acc[i][2] + bv[2]; v0.w = acc[i][3] + bv[3];
        v1.x = acc[i][4] + bv[4]; v1.y = acc[i][5] + bv[5];
        v1.z = acc[i][6] + bv[6]; v1.w = acc[i][7] + bv[7];
        *(float4*)(Crow)     = v0;
        *(float4*)(Crow + 4) = v1;
    }
}

// ---------------------------------------------------------------------------
// Kernel 2: g_S[z][n][m] = max(pe[b,n,m,:].pos_w[g] + pos_b[g], eps)
// block = (b, n, 64 m's); all 16 g per block so pe is read exactly once.
// Vectorized inner loop: float4 smem reads.
// ---------------------------------------------------------------------------
__global__ __launch_bounds__(256) void posw_kernel(const float* __restrict__ pe,
                                                   const float* __restrict__ pw,
                                                   const float* __restrict__ pb)
{
    __shared__ float pe_s[64][68];
    __shared__ float pw_s[Gg * Ee];
    __shared__ float pb_s[Gg];
    const int tid = threadIdx.x;
    const int m0  = blockIdx.x * 64;
    const int n   = blockIdx.y;
    const int b   = blockIdx.z;

    for (int i = tid; i < Gg * Ee; i += 256) pw_s[i] = pw[i];
    if (tid < Gg) pb_s[tid] = pb[tid];

    const float4* src = (const float4*)(pe + (((size_t)(b * Nn + n)) * Mm + m0) * Ee);
#pragma unroll
    for (int r = 0; r < 4; r++) {
        int i4 = tid + 256 * r;
        float4 v = src[i4];
        int mm = i4 >> 4;
        int e4 = (i4 & 15) * 4;
        pe_s[mm][e4 + 0] = v.x; pe_s[mm][e4 + 1] = v.y;
        pe_s[mm][e4 + 2] = v.z; pe_s[mm][e4 + 3] = v.w;
    }
    __syncthreads();

    const int m  = tid & 63;
    const int gb = (tid >> 6) * 4;
    float acc[4] = {0.f, 0.f, 0.f, 0.f};
#pragma unroll
    for (int e0 = 0; e0 < 64; e0 += 4) {
        float4 pv = *(const float4*)(&pe_s[m][e0]);
#pragma unroll
        for (int p = 0; p < 4; p++) {
            float4 w4 = *(const float4*)(&pw_s[(gb + p) * Ee + e0]);
            acc[p] += pv.x * w4.x + pv.y * w4.y + pv.z * w4.z + pv.w * w4.w;
        }
    }
    size_t base = ((size_t)(b * Gg + gb) * Nn + n) * Mm + m0 + m;
#pragma unroll
    for (int p = 0; p < 4; p++) {
        g_S[base + (size_t)p * Nn * Mm] = fmaxf(acc[p] + pb_s[gb + p], EPSv);
    }
}

// ---------------------------------------------------------------------------
// Kernel 3: aff + exp + weight + rowsum, fused.
// S[z][n][m] <- S[z][n][m] * exp(0.125 * q.k);  g_sum[z][n] += row sum.
// 128x128 tile per block, 8x8 per thread, K=64 in two 32-chunks.
// ---------------------------------------------------------------------------
__global__ __launch_bounds__(256) void aff_fused()
{
    __shared__ float Qs[32][132];
    __shared__ float Ks[32][132];
    const int tid = threadIdx.x;
    const int z   = blockIdx.z;
    const int b   = z >> 4, g = z & 15;
    const int n0  = blockIdx.y * 128;
    const int m0  = blockIdx.x * 128;
    const float* Qb = g_QKV + (size_t)b * Nn * 3072 + g * 64;
    const float* Kb = Qb + 1024;
    const int tx = tid & 15, ty = tid >> 4;

    float acc[8][8];
#pragma unroll
    for (int i = 0; i < 8; i++)
#pragma unroll
        for (int j = 0; j < 8; j++) acc[i][j] = 0.f;

    for (int d0 = 0; d0 < 64; d0 += 32) {
#pragma unroll
        for (int r = 0; r < 4; r++) {
            int i4 = tid + 256 * r;
            int rr = i4 >> 3;
            int c4 = (i4 & 7) * 4;
            float4 q = *(const float4*)(Qb + (size_t)(n0 + rr) * 3072 + d0 + c4);
            float4 k = *(const float4*)(Kb + (size_t)(m0 + rr) * 3072 + d0 + c4);
            Qs[c4 + 0][rr] = q.x; Qs[c4 + 1][rr] = q.y;
            Qs[c4 + 2][rr] = q.z; Qs[c4 + 3][rr] = q.w;
            Ks[c4 + 0][rr] = k.x; Ks[c4 + 1][rr] = k.y;
            Ks[c4 + 2][rr] = k.z; Ks[c4 + 3][rr] = k.w;
        }
        __syncthreads();
#pragma unroll
        for (int kk = 0; kk < 32; kk++) {
            float a[8], w[8];
            *(float4*)(a)     = *(const float4*)(&Qs[kk][ty * 8]);
            *(float4*)(a + 4) = *(const float4*)(&Qs[kk][ty * 8 + 4]);
            *(float4*)(w)     = *(const float4*)(&Ks[kk][tx * 8]);
            *(float4*)(w + 4) = *(const float4*)(&Ks[kk][tx * 8 + 4]);
#pragma unroll
            for (int i = 0; i < 8; i++)
#pragma unroll
                for (int j = 0; j < 8; j++)
                    acc[i][j] += a[i] * w[j];
        }
        __syncthreads();
    }

    // Epilogue: read weights, apply exp, write back, accumulate row sums.
#pragma unroll
    for (int i = 0; i < 8; i++) {
        int row = n0 + ty * 8 + i;
        float* Sp = g_S + ((size_t)z * Nn + row) * Mm + m0 + tx * 8;
        float4 w0 = *(const float4*)(Sp);
        float4 w1 = *(const float4*)(Sp + 4);
        float4 o0, o1;
        o0.x = w0.x * __expf(0.125f * acc[i][0]);
        o0.y = w0.y * __expf(0.125f * acc[i][1]);
        o0.z = w0.z * __expf(0.125f * acc[i][2]);
        o0.w = w0.w * __expf(0.125f * acc[i][3]);
        o1.x = w1.x * __expf(0.125f * acc[i][4]);
        o1.y = w1.y * __expf(0.125f * acc[i][5]);
        o1.z = w1.z * __expf(0.125f * acc[i][6]);
        o1.w = w1.w * __expf(0.125f * acc[i][7]);
        *(float4*)(Sp)     = o0;
        *(float4*)(Sp + 4) = o1;

        float rs = o0.x + o0.y + o0.z + o0.w + o1.x + o1.y + o1.z + o1.w;
        // reduce across the 16 tx lanes (lane = (ty&1)*16 + tx)
        rs += __shfl_xor_sync(0xffffffffu, rs, 1);
        rs += __shfl_xor_sync(0xffffffffu, rs, 2);
        rs += __shfl_xor_sync(0xffffffffu, rs, 4);
        rs += __shfl_xor_sync(0xffffffffu, rs, 8);
        if (tx == 0)
            atomicAdd(&g_sum[(size_t)z * Nn + row], rs);
    }
}

// ---------------------------------------------------------------------------
// Kernel 4: out[b,n,g*64+o] = (1/sum[z,n]) * sum_m S[z][n][m] * V[b,m,g*64+o]
//                             + conv_b[g*64+o]
// 128n x 64o tile per (b,g); 8x4 per thread; m in chunks of 32 (P transposed).
// ---------------------------------------------------------------------------
__global__ __launch_bounds__(256) void pv_kernel(const float* __restrict__ cb,
                                                 float* __restrict__ out)
{
    __shared__ float Ps[32][132];
    __shared__ float Vs[32][68];
    const int tid = threadIdx.x;
    const int z   = blockIdx.y;
    const int b   = z >> 4, g = z & 15;
    const int n0  = blockIdx.x * 128;
    const int tx  = tid & 15, ty = tid >> 4;
    const float* Vb = g_QKV + (size_t)b * Nn * 3072 + 2048 + g * 64;
    const float* Pb = g_S + ((size_t)z * Nn + n0) * Mm;

    float acc[8][4];
#pragma unroll
    for (int i = 0; i < 8; i++)
#pragma unroll
        for (int j = 0; j < 4; j++) acc[i][j] = 0.f;

    for (int m0 = 0; m0 < Mm; m0 += 32) {
#pragma unroll
        for (int r = 0; r < 4; r++) {
            int i4 = tid + 256 * r;
            int rr = i4 >> 3;           // n index 0..127
            int c4 = (i4 & 7) * 4;      // m offset 0..28
            float4 p = *(const float4*)(Pb + (size_t)rr * Mm + m0 + c4);
            Ps[c4 + 0][rr] = p.x; Ps[c4 + 1][rr] = p.y;
            Ps[c4 + 2][rr] = p.z; Ps[c4 + 3][rr] = p.w;
        }
#pragma unroll
        for (int r = 0; r < 2; r++) {
            int i4 = tid + 256 * r;
            int mm = i4 >> 4;           // m offset 0..31
            int o4 = (i4 & 15) * 4;     // o 0..60
            *(float4*)(&Vs[mm][o4]) =
                *(const float4*)(Vb + (size_t)(m0 + mm) * 3072 + o4);
        }
        __syncthreads();
#pragma unroll
        for (int kk = 0; kk < 32; kk++) {
            float a[8];
            *(float4*)(a)     = *(const float4*)(&Ps[kk][ty * 8]);
            *(float4*)(a + 4) = *(const float4*)(&Ps[kk][ty * 8 + 4]);
            float4 v = *(const float4*)(&Vs[kk][tx * 4]);
#pragma unroll
            for (int i = 0; i < 8; i++) {
                acc[i][0] += a[i] * v.x;
                acc[i][1] += a[i] * v.y;
                acc[i][2] += a[i] * v.z;
                acc[i][3] += a[i] * v.w;
            }
        }
        __syncthreads();
    }

    float b0 = cb[g * 64 + tx * 4 + 0];
    float b1 = cb[g * 64 + tx * 4 + 1];
    float b2 = cb[g * 64 + tx * 4 + 2];
    float b3 = cb[g * 64 + tx * 4 + 3];
#pragma unroll
    for (int i = 0; i < 8; i++) {
        int row = n0 + ty * 8 + i;
        float iv = 1.0f / g_sum[(size_t)z * Nn + row];
        float4 res;
        res.x = acc[i][0] * iv + b0;
        res.y = acc[i][1] * iv + b1;
        res.z = acc[i][2] * iv + b2;
        res.w = acc[i][3] * iv + b3;
        *(float4*)(&out[(size_t)(b * Nn + row) * 1024 + g * 64 + tx * 4]) = res;
    }
}

// ---------------------------------------------------------------------------
extern "C" void kernel_launch(void* const* d_in, const int* in_sizes, int n_in,
                              void* d_out, int out_size)
{
    const float* roi = (const float*)d_in[0];
    const float* pe  = (const float*)d_in[1];
    const float* pw  = (const float*)d_in[2];
    const float* pb  = (const float*)d_in[3];
    const float* qw  = (const float*)d_in[4];
    const float* qb  = (const float*)d_in[5];
    const float* kw  = (const float*)d_in[6];
    const float* kb  = (const float*)d_in[7];
    const float* cw  = (const float*)d_in[8];
    const float* cb  = (const float*)d_in[9];
    float* out = (float*)d_out;

    const int Bb = in_sizes[0] / (Nn * Ff);  // batch (2)

    // 0) zero row-sum accumulators
    init_sums<<<(Bb * Gg * Nn + 255) / 256, 256>>>(Bb * Gg * Nn);

    // 1) Q, K, V projections (one launch; V bias = conv_b handled in pv epilogue)
    qkv_gemm_all<<<dim3(24, (Bb * Nn) / 128), 256>>>(roi, qw, kw, cw, qb, kb);

    // 2) clamped position weights -> g_S   (reads pe exactly once)
    posw_kernel<<<dim3(Mm / 64, Nn, Bb), 256>>>(pe, pw, pb);

    // 3) q.k logits + exp + weight + row sums, fused, in-place on g_S
    aff_fused<<<dim3(Mm / 128, Nn / 128, Bb * Gg), 256>>>();

    // 4) grouped P @ V with normalization + conv bias
    pv_kernel<<<dim3(Nn / 128, Bb * Gg), 256>>>(cb, out);
}